// round 11
// baseline (speedup 1.0000x reference)
#include <cuda_runtime.h>
#include <cuda_bf16.h>

typedef unsigned long long ull;

#define MT   4096
#define DD   2048
#define HH   256
#define NQ   8
#define NKV  4
#define TSEQ 2048
#define WIN  1024

// ---------------- static device scratch (no allocations) --------------------
__device__ __align__(256) float g_q[(size_t)NQ  * MT * HH];
__device__ __align__(256) float g_k[(size_t)NKV * MT * HH];
__device__ __align__(256) float g_v[(size_t)NKV * MT * HH];
__device__ __align__(256) float g_att[(size_t)MT * DD];

// ---------------- f32x2 packed helpers --------------------------------------
__device__ __forceinline__ ull pk2(float lo, float hi) {
    ull r; asm("mov.b64 %0, {%1,%2};" : "=l"(r) : "f"(lo), "f"(hi)); return r;
}
__device__ __forceinline__ float2 upk2(ull v) {
    float2 r; asm("mov.b64 {%0,%1}, %2;" : "=f"(r.x), "=f"(r.y) : "l"(v)); return r;
}
__device__ __forceinline__ void ffma2(ull& d, ull a, ull b) {
    asm("fma.rn.f32x2 %0, %1, %2, %0;" : "+l"(d) : "l"(a), "l"(b));
}
__device__ __forceinline__ ull mul2(ull a, ull b) {
    ull r; asm("mul.rn.f32x2 %0, %1, %2;" : "=l"(r) : "l"(a), "l"(b)); return r;
}

// ---------------- f32x2 SGEMM: C = A(4096x2048) @ B(2048 x N) ----------------
// 128x128x8 tile, 256 threads, 8x8 per-thread micro-tile (8 rows x 4 f32x2).
#define ASTR 132
__global__ __launch_bounds__(256, 2)
void gemm_f32x2(const float* __restrict__ A, const float* __restrict__ B0,
                float* __restrict__ C0, int ldb, int ldc,
                long bstride, long cstride)
{
    __shared__ __align__(16) float As[8 * ASTR];
    __shared__ __align__(16) float Bs[8 * 128];

    const float* B = B0 + (long)blockIdx.z * bstride;
    float*       C = C0 + (long)blockIdx.z * cstride;

    const int tid = threadIdx.x;
    const int tx  = tid & 15;
    const int ty  = tid >> 4;
    const int m0  = blockIdx.y * 128;
    const int n0  = blockIdx.x * 128;
    const int KD  = DD;

    const int ar = tid >> 1;
    const int ak = (tid & 1) * 4;
    const int br = tid >> 5;
    const int bc = (tid & 31) * 4;

    const float* Aptr = A + (long)(m0 + ar) * KD + ak;
    const float* Bptr = B + (long)br * ldb + n0 + bc;

    ull acc[8][4];
    #pragma unroll
    for (int i = 0; i < 8; i++)
        #pragma unroll
        for (int p = 0; p < 4; p++) acc[i][p] = 0ull;

    float4 a4 = *(const float4*)Aptr;
    float4 b4 = *(const float4*)Bptr;

    for (int k0 = 0; k0 < KD; k0 += 8) {
        As[(ak + 0) * ASTR + ar] = a4.x;
        As[(ak + 1) * ASTR + ar] = a4.y;
        As[(ak + 2) * ASTR + ar] = a4.z;
        As[(ak + 3) * ASTR + ar] = a4.w;
        *(float4*)&Bs[br * 128 + bc] = b4;
        __syncthreads();

        if (k0 + 8 < KD) {
            a4 = *(const float4*)(Aptr + k0 + 8);
            b4 = *(const float4*)(Bptr + (long)(k0 + 8) * ldb);
        }

        #pragma unroll
        for (int kk = 0; kk < 8; kk++) {
            float4 fa0 = *(const float4*)&As[kk * ASTR + ty * 4];
            float4 fa1 = *(const float4*)&As[kk * ASTR + ty * 4 + 64];
            ulonglong2 fb0 = *(const ulonglong2*)&Bs[kk * 128 + tx * 4];
            ulonglong2 fb1 = *(const ulonglong2*)&Bs[kk * 128 + tx * 4 + 64];
            float av[8] = {fa0.x, fa0.y, fa0.z, fa0.w, fa1.x, fa1.y, fa1.z, fa1.w};
            #pragma unroll
            for (int i = 0; i < 8; i++) {
                ull pa = pk2(av[i], av[i]);
                ffma2(acc[i][0], pa, fb0.x);
                ffma2(acc[i][1], pa, fb0.y);
                ffma2(acc[i][2], pa, fb1.x);
                ffma2(acc[i][3], pa, fb1.y);
            }
        }
        __syncthreads();
    }

    #pragma unroll
    for (int i = 0; i < 8; i++) {
        int row = m0 + ty * 4 + (i >> 2) * 64 + (i & 3);
        #pragma unroll
        for (int c = 0; c < 2; c++) {
            float2 lo = upk2(acc[i][2 * c]);
            float2 hi = upk2(acc[i][2 * c + 1]);
            float4 o = make_float4(lo.x, lo.y, hi.x, hi.y);
            *(float4*)&C[(long)row * ldc + n0 + tx * 4 + 64 * c] = o;
        }
    }
}

// ---------------- RMSNorm + RoPE + q scale (in place) ------------------------
__global__ void normrope_kernel(float* __restrict__ gq, float* __restrict__ gk,
                                const int* __restrict__ positions,
                                const float* __restrict__ qns,
                                const float* __restrict__ kns)
{
    const int m    = blockIdx.x;
    const int head = blockIdx.y;
    float* buf; const float* nsc; float omult;
    if (head < NQ) { buf = gq + ((long)head * MT + m) * HH;        nsc = qns; omult = 0.0625f; }
    else           { buf = gk + ((long)(head - NQ) * MT + m) * HH; nsc = kns; omult = 1.0f; }

    const int t = threadIdx.x;   // 64 threads
    __shared__ float row[256];
    __shared__ float red[2];

    float4 v = *(const float4*)&buf[t * 4];
    float ss = v.x * v.x + v.y * v.y + v.z * v.z + v.w * v.w;
    #pragma unroll
    for (int o = 16; o > 0; o >>= 1) ss += __shfl_xor_sync(0xffffffffu, ss, o);
    if ((t & 31) == 0) red[t >> 5] = ss;
    __syncthreads();
    float r = rsqrtf((red[0] + red[1]) * (1.0f / 256.0f) + 1e-6f);

    float4 sc = *(const float4*)&nsc[t * 4];
    row[t * 4 + 0] = v.x * r * (1.0f + sc.x);
    row[t * 4 + 1] = v.y * r * (1.0f + sc.y);
    row[t * 4 + 2] = v.z * r * (1.0f + sc.z);
    row[t * 4 + 3] = v.w * r * (1.0f + sc.w);
    __syncthreads();

    if (t < 32) {
        float pos = (float)positions[m];
        #pragma unroll
        for (int c = 0; c < 4; c++) {
            int h = t * 4 + c;                          // 0..127
            float ts = powf(10000.0f, (float)h * (1.0f / 128.0f));
            float ang = pos / ts;
            float sn, cs;
            sincosf(ang, &sn, &cs);
            float f = row[h], s = row[h + 128];
            buf[h]       = (f * cs - s * sn) * omult;
            buf[h + 128] = (s * cs + f * sn) * omult;
        }
    }
}

// ---------------- flash attention, sliding window 1024 -----------------------
// Strides MUST be multiples of 4 floats: the tile loaders use float4 on
// row*STRIDE + d offsets, and 16B alignment requires offset % 4 == 0.
// (258 was the R9/R10 misaligned-address bug: odd rows gave offset % 4 == 2.)
#define BQ    64
#define QSTR  260
#define KSTR  260
#define VSTR  260
#define PSTR  33
#define ATTN_SMEM (((BQ + 32 + 32) * 260 + BQ * PSTR) * 4)

__device__ __forceinline__ float redmax16(float v) {
    #pragma unroll
    for (int o = 8; o > 0; o >>= 1) v = fmaxf(v, __shfl_xor_sync(0xffffffffu, v, o));
    return v;
}
__device__ __forceinline__ float redsum16(float v) {
    #pragma unroll
    for (int o = 8; o > 0; o >>= 1) v += __shfl_xor_sync(0xffffffffu, v, o);
    return v;
}

__global__ __launch_bounds__(256, 1)
void attn_kernel(const float* __restrict__ qb, const float* __restrict__ kb,
                 const float* __restrict__ vb, float* __restrict__ ob)
{
    extern __shared__ __align__(16) float sm[];
    float* Qs = sm;                  // [64][260]
    float* Ks = Qs + BQ * QSTR;      // [32][260]
    float* Vs = Ks + 32 * KSTR;      // [32][260]
    float* Ps = Vs + 32 * VSTR;      // [64][33]

    const int tid = threadIdx.x;
    const int tx  = tid & 15;
    const int ty  = tid >> 4;
    const int t0  = blockIdx.x * BQ;
    const int n   = blockIdx.y;
    const int b   = blockIdx.z;
    const int kvh = n >> 1;

    const float* qptr = qb + ((long)n   * MT + b * TSEQ + t0) * HH;
    const float* kptr = kb + ((long)kvh * MT + b * TSEQ)      * HH;
    const float* vptr = vb + ((long)kvh * MT + b * TSEQ)      * HH;

    for (int e = tid * 4; e < BQ * HH; e += 1024) {
        int q = e >> 8, d = e & 255;
        *(float4*)&Qs[q * QSTR + d] = *(const float4*)&qptr[q * HH + d];
    }

    const int q0 = ty * 4;
    float mrow[4] = {-1e30f, -1e30f, -1e30f, -1e30f};
    float lrow[4] = {0.f, 0.f, 0.f, 0.f};
    ull O2[4][8];
    #pragma unroll
    for (int i = 0; i < 4; i++)
        #pragma unroll
        for (int p = 0; p < 8; p++) O2[i][p] = 0ull;

    int s_begin = t0 - (WIN - 1); if (s_begin < 0) s_begin = 0;
    s_begin &= ~31;
    const int s_end = t0 + BQ - 1;

    for (int s0 = s_begin; s0 <= s_end; s0 += 32) {
        __syncthreads();
        for (int e = tid * 4; e < 32 * HH; e += 1024) {
            int j = e >> 8, d = e & 255;
            *(float4*)&Ks[j * KSTR + d] = *(const float4*)&kptr[(long)(s0 + j) * HH + d];
            *(float4*)&Vs[j * VSTR + d] = *(const float4*)&vptr[(long)(s0 + j) * HH + d];
        }
        __syncthreads();

        // S = Q K^T (f32x2 over d-pairs); thread handles keys tx and tx+16
        ull S2[4][2];
        #pragma unroll
        for (int i = 0; i < 4; i++) { S2[i][0] = 0ull; S2[i][1] = 0ull; }
        #pragma unroll 4
        for (int d2 = 0; d2 < 128; d2++) {
            ull kp0 = *(const ull*)&Ks[tx * KSTR + 2 * d2];
            ull kp1 = *(const ull*)&Ks[(tx + 16) * KSTR + 2 * d2];
            #pragma unroll
            for (int i = 0; i < 4; i++) {
                ull qp = *(const ull*)&Qs[(q0 + i) * QSTR + 2 * d2];
                ffma2(S2[i][0], qp, kp0);
                ffma2(S2[i][1], qp, kp1);
            }
        }

        float fac[4];
        #pragma unroll
        for (int i = 0; i < 4; i++) {
            float2 f0 = upk2(S2[i][0]);
            float2 f1 = upk2(S2[i][1]);
            float sv0 = f0.x + f0.y;
            float sv1 = f1.x + f1.y;
            int t = t0 + q0 + i;
            int sA = s0 + tx, sB = s0 + tx + 16;
            bool v0 = (sA <= t) && (sA > t - WIN);
            bool v1 = (sB <= t) && (sB > t - WIN);
            if (!v0) sv0 = -1e30f;
            if (!v1) sv1 = -1e30f;

            float mx = redmax16(fmaxf(sv0, sv1));
            float mn = fmaxf(mrow[i], mx);
            fac[i] = __expf(mrow[i] - mn);
            mrow[i] = mn;
            float p0 = v0 ? __expf(sv0 - mn) : 0.f;
            float p1 = v1 ? __expf(sv1 - mn) : 0.f;
            Ps[(q0 + i) * PSTR + tx]      = p0;
            Ps[(q0 + i) * PSTR + tx + 16] = p1;
            lrow[i] = lrow[i] * fac[i] + redsum16(p0 + p1);
        }
        __syncwarp();

        // rescale O
        #pragma unroll
        for (int i = 0; i < 4; i++) {
            ull f = pk2(fac[i], fac[i]);
            #pragma unroll
            for (int p = 0; p < 8; p++) O2[i][p] = mul2(O2[i][p], f);
        }

        // O += P V ; thread owns h = tx*16 .. tx*16+15, j staggered by tx
        #pragma unroll 4
        for (int j = 0; j < 32; j++) {
            int jj = (j + tx) & 31;
            const ull* vrow = (const ull*)&Vs[jj * VSTR + tx * 16];
            ull pp[4];
            #pragma unroll
            for (int i = 0; i < 4; i++) {
                float pv = Ps[(q0 + i) * PSTR + jj];
                pp[i] = pk2(pv, pv);
            }
            #pragma unroll
            for (int p = 0; p < 8; p++) {
                ull vv = vrow[p];
                #pragma unroll
                for (int i = 0; i < 4; i++) ffma2(O2[i][p], pp[i], vv);
            }
        }
    }

    // normalize and write to g_att[m][n*256 + h]
    #pragma unroll
    for (int i = 0; i < 4; i++) {
        float inv = 1.0f / lrow[i];
        ull s = pk2(inv, inv);
        long m = (long)b * TSEQ + t0 + q0 + i;
        #pragma unroll
        for (int p = 0; p < 8; p++) {
            float2 o = upk2(mul2(O2[i][p], s));
            *(float2*)&ob[m * DD + n * HH + tx * 16 + 2 * p] = o;
        }
    }
}

// ---------------- launcher ---------------------------------------------------
extern "C" void kernel_launch(void* const* d_in, const int* in_sizes, int n_in,
                              void* d_out, int out_size) {
    const float* x    = (const float*)d_in[0];
    const int*   pos  = (const int*)  d_in[1];
    const float* q_w  = (const float*)d_in[2];
    const float* k_w  = (const float*)d_in[3];
    const float* v_w  = (const float*)d_in[4];
    const float* o_w  = (const float*)d_in[5];
    const float* qns  = (const float*)d_in[6];
    const float* kns  = (const float*)d_in[7];
    float* out = (float*)d_out;

    float *pq, *pk, *pv, *patt;
    cudaGetSymbolAddress((void**)&pq,   g_q);
    cudaGetSymbolAddress((void**)&pk,   g_k);
    cudaGetSymbolAddress((void**)&pv,   g_v);
    cudaGetSymbolAddress((void**)&patt, g_att);

    cudaFuncSetAttribute(attn_kernel,
                         cudaFuncAttributeMaxDynamicSharedMemorySize, ATTN_SMEM);

    // Q/K/V projections: per-head GEMM via grid.z
    gemm_f32x2<<<dim3(2, 32, NQ),  256>>>(x, q_w, pq, HH, HH,
                                          (long)DD * HH, (long)MT * HH);
    gemm_f32x2<<<dim3(2, 32, NKV), 256>>>(x, k_w, pk, HH, HH,
                                          (long)DD * HH, (long)MT * HH);
    gemm_f32x2<<<dim3(2, 32, NKV), 256>>>(x, v_w, pv, HH, HH,
                                          (long)DD * HH, (long)MT * HH);

    // RMSNorm + RoPE (+ q * H^-0.5)
    normrope_kernel<<<dim3(MT, NQ + NKV), 64>>>(pq, pk, pos, qns, kns);

    // windowed attention -> g_att [m][n*H+h]
    attn_kernel<<<dim3(TSEQ / BQ, NQ, 2), 256, ATTN_SMEM>>>(pq, pk, pv, patt);

    // output projection
    gemm_f32x2<<<dim3(16, 32, 1), 256>>>(patt, o_w, out, DD, DD, 0, 0);
}